// round 8
// baseline (speedup 1.0000x reference)
#include <cuda_runtime.h>

// SoftRank, value-range-split bucket kernel.
// out[b,j,c] = (1/N) * sum_i sigmoid(1000*(x[b,j,c]-x[b,i,c]))
//
// grid = 256: two CTAs per (b,c) column, split by value range
//   r=0: handles outputs with v <  0, histogram range [-5-W,  +W)
//   r=1: handles outputs with v >= 0, histogram range [  -W, 5+W)
// Each CTA (512 threads, 2 values/thread):
//   - loads the full column
//   - counts below-margin values via warp ballots (no per-element atomics)
//   - histograms in-margin values into 1024 buckets (smem atomics, ~512/CTA)
//   - block exclusive prefix sum (2 buckets/thread), sentinel = total
//   - scatters in-margin values into bucket order
//   - epilogue only for in-range outputs:
//       result = below + prefix(lower buckets) + branchless tanh window scan
// Two CTAs co-resident per SM interleave their barrier-bounded phases,
// hiding the latency exposure that capped the single-CTA version.

#define NN      1024
#define CC      16
#define TPB     512
#define NBKT    1024
#define WINDOW  0.009f            // |1000*(v-s)| >= 9 outside -> tail err ~1.2e-4

__device__ __forceinline__ float fast_tanh(float x) {
    float r;
    asm("tanh.approx.f32 %0, %1;" : "=f"(r) : "f"(x));
    return r;
}

__global__ __launch_bounds__(TPB) void softrank_split_kernel(
    const float* __restrict__ x, float* __restrict__ out)
{
    const int bx  = blockIdx.x;
    const int col = bx >> 1;             // 0..127
    const int r   = bx & 1;              // range half
    const int b   = col >> 4;
    const int c   = col & (CC - 1);

    __shared__ unsigned cnt[NBKT + 1];   // counts -> exclusive prefix; [NBKT]=total
    __shared__ float    skey[NN];        // in-margin values in bucket order
    __shared__ unsigned wsum[16];
    __shared__ unsigned below_s;

    const float rlo  = r ? (-WINDOW) : (-5.0f - WINDOW);       // margin low edge
    const float BW   = (5.0f + 2.0f * WINDOW) / (float)NBKT;   // bucket width
    const float INVW = 1.0f / BW;
    const float rhi  = rlo + (float)NBKT * BW;                 // margin high edge

    const int t    = threadIdx.x;
    const int lane = t & 31;
    const int wid  = t >> 5;

    // ---- load both rows early (long latency first) ----
    const int base = b * (NN * CC) + c;
    const float v0 = x[base + t * CC];
    const float v1 = x[base + (t + TPB) * CC];

    cnt[2 * t]     = 0u;
    cnt[2 * t + 1] = 0u;
    if (t == 0) below_s = 0u;
    __syncthreads();

    // ---- classify + histogram in-margin, ballot-count below-margin ----
    const bool in0 = (v0 >= rlo) && (v0 < rhi);
    const bool in1 = (v1 >= rlo) && (v1 < rhi);
    int bk0 = (int)((v0 - rlo) * INVW); bk0 = min(max(bk0, 0), NBKT - 1);
    int bk1 = (int)((v1 - rlo) * INVW); bk1 = min(max(bk1, 0), NBKT - 1);

    unsigned slot0 = 0u, slot1 = 0u;
    if (in0) slot0 = atomicAdd(&cnt[bk0], 1u);
    if (in1) slot1 = atomicAdd(&cnt[bk1], 1u);

    const unsigned bel = __popc(__ballot_sync(0xffffffffu, v0 < rlo))
                       + __popc(__ballot_sync(0xffffffffu, v1 < rlo));
    if (lane == 0 && bel) atomicAdd(&below_s, bel);
    __syncthreads();

    // ---- block exclusive prefix sum over 1024 buckets, 2 per thread ----
    const unsigned c0 = cnt[2 * t], c1 = cnt[2 * t + 1];
    const unsigned tsum = c0 + c1;
    unsigned inc = tsum;
    #pragma unroll
    for (int j = 1; j < 32; j <<= 1) {
        unsigned n = __shfl_up_sync(0xffffffffu, inc, j);
        if (lane >= j) inc += n;
    }
    if (lane == 31) wsum[wid] = inc;
    __syncthreads();
    if (wid == 0) {
        unsigned w  = (lane < 16) ? wsum[lane] : 0u;
        unsigned wi = w;
        #pragma unroll
        for (int j = 1; j < 32; j <<= 1) {
            unsigned n = __shfl_up_sync(0xffffffffu, wi, j);
            if (lane >= j) wi += n;
        }
        if (lane < 16) wsum[lane] = wi - w;   // exclusive warp offsets
    }
    __syncthreads();
    const unsigned excl = wsum[wid] + (inc - tsum);
    cnt[2 * t]     = excl;
    cnt[2 * t + 1] = excl + c0;
    if (t == TPB - 1) cnt[NBKT] = wsum[15] + inc;   // total scattered (sentinel)
    __syncthreads();

    // ---- scatter in-margin values into bucket order ----
    if (in0) skey[cnt[bk0] + slot0] = v0;
    if (in1) skey[cnt[bk1] + slot1] = v1;
    __syncthreads();

    const float below = (float)below_s;

    // ---- epilogue for this CTA's value range only ----
    #pragma unroll
    for (int pass = 0; pass < 2; ++pass) {
        const float v   = pass ? v1 : v0;
        const int   row = pass ? (t + TPB) : t;
        const bool  own = r ? (v >= 0.0f) : (v < 0.0f);
        if (!own) continue;

        int blo = (int)((v - WINDOW - rlo) * INVW); blo = min(max(blo, 0), NBKT - 1);
        int bhi = (int)((v + WINDOW - rlo) * INVW); bhi = min(max(bhi, 0), NBKT - 1);

        const unsigned start = cnt[blo];
        const unsigned end   = cnt[bhi + 1];

        const float a = 500.0f * v;
        float s0 = 0.0f, s1 = 0.0f;
        unsigned i = start;
        for (; i + 1 < end; i += 2) {
            s0 += fast_tanh(fmaf(-500.0f, skey[i],     a));
            s1 += fast_tanh(fmaf(-500.0f, skey[i + 1], a));
        }
        if (i < end)
            s0 += fast_tanh(fmaf(-500.0f, skey[i], a));

        const float sum = below + (float)start
                        + 0.5f * (float)(end - start)
                        + 0.5f * (s0 + s1);

        out[base + row * CC] = sum * (1.0f / (float)NN);
    }
}

extern "C" void kernel_launch(void* const* d_in, const int* in_sizes, int n_in,
                              void* d_out, int out_size)
{
    const float* x = (const float*)d_in[0];
    float* out = (float*)d_out;
    softrank_split_kernel<<<2 * 8 * CC, TPB>>>(x, out);
}

// round 9
// speedup vs baseline: 1.3092x; 1.3092x over previous
#include <cuda_runtime.h>

// SoftRank via bucket-histogram rank + narrow tanh window.
// out[b,j,c] = (1/N) * sum_i sigmoid(1000*(x[b,j,c]-x[b,i,c]))
//
// Per (b,c) column (one CTA, 1024 threads):
//   1. histogram 1024 values into 4096 buckets over [-5,5] (smem atomics)
//   2. block exclusive prefix sum, 4 buckets/thread, all warps redundantly
//      scan the warp totals (no wid-0 wait), sentinel cnt[4096]=N
//   3. scatter values into bucket order
//   4. own-element epilogue: rank = prefix of lower buckets (each exactly 1,
//      tail err e^-4.5 ~ 1% of a single sigmoid, /N after), plus branchless
//      tanh.approx scan of the ~4-element bucket window (saturation keeps
//      out-of-window scanned elements exact).

#define NN       1024
#define CC       16
#define BB       8
#define NBKT     4096
#define RANGE_LO (-5.0f)
#define INV_W    409.6f          // NBKT / 10.0
#define WINDOW   0.0045f         // |1000*d| >= 4.5 outside -> rel err ~2e-5

__device__ __forceinline__ float fast_tanh(float x) {
    float r;
    asm("tanh.approx.f32 %0, %1;" : "=f"(r) : "f"(x));
    return r;
}

__device__ __forceinline__ int bucket_of(float v) {
    int b = (int)((v - RANGE_LO) * INV_W);
    return min(max(b, 0), NBKT - 1);
}

__global__ __launch_bounds__(NN) void softrank_bucket4_kernel(
    const float* __restrict__ x, float* __restrict__ out)
{
    const int b = blockIdx.x >> 4;       // / CC
    const int c = blockIdx.x & (CC - 1); // % CC

    __shared__ unsigned cnt[NBKT + 4];   // counts -> exclusive prefix; [NBKT]=N sentinel
    __shared__ float    skey[NN];        // values in bucket order
    __shared__ unsigned wsum[32];

    const int t    = threadIdx.x;
    const int lane = t & 31;
    const int wid  = t >> 5;

    const float v = x[(b * NN + t) * CC + c];   // long-latency, issued first
    ((uint4*)cnt)[t] = make_uint4(0u, 0u, 0u, 0u);
    const int bk = bucket_of(v);
    __syncthreads();

    // ---- histogram; slot = within-bucket ordinal ----
    const unsigned slot = atomicAdd(&cnt[bk], 1u);
    __syncthreads();

    // ---- block exclusive prefix sum over 4096 counts, 4 per thread ----
    const uint4 c4 = ((uint4*)cnt)[t];
    const unsigned tsum = c4.x + c4.y + c4.z + c4.w;

    unsigned inc = tsum;                 // warp-inclusive scan of thread sums
    #pragma unroll
    for (int j = 1; j < 32; j <<= 1) {
        unsigned n = __shfl_up_sync(0xffffffffu, inc, j);
        if (lane >= j) inc += n;
    }
    if (lane == 31) wsum[wid] = inc;
    __syncthreads();

    // every warp redundantly scans the 32 warp totals (no wid-0 wait)
    unsigned wv = wsum[lane];
    unsigned wi = wv;
    #pragma unroll
    for (int j = 1; j < 32; j <<= 1) {
        unsigned n = __shfl_up_sync(0xffffffffu, wi, j);
        if (lane >= j) wi += n;
    }
    const unsigned wexcl = __shfl_sync(0xffffffffu, wi - wv, wid);

    const unsigned texcl = wexcl + (inc - tsum);
    uint4 p4;
    p4.x = texcl;
    p4.y = texcl + c4.x;
    p4.z = texcl + c4.x + c4.y;
    p4.w = texcl + c4.x + c4.y + c4.z;
    ((uint4*)cnt)[t] = p4;
    if (t == 0) cnt[NBKT] = (unsigned)NN;        // branchless end lookup
    __syncthreads();

    // ---- scatter into bucket order ----
    skey[cnt[bk] + slot] = v;
    __syncthreads();

    // ---- own-element epilogue ----
    const int b_lo = bucket_of(v - WINDOW);
    const int b_hi = bucket_of(v + WINDOW);

    const unsigned start = cnt[b_lo];
    const unsigned end   = cnt[b_hi + 1];

    const float a = 500.0f * v;
    float s0 = 0.0f, s1 = 0.0f;
    unsigned i = start;
    for (; i + 1 < end; i += 2) {        // 2-way ILP on LDS + MUFU
        s0 += fast_tanh(fmaf(-500.0f, skey[i],     a));
        s1 += fast_tanh(fmaf(-500.0f, skey[i + 1], a));
    }
    if (i < end)
        s0 += fast_tanh(fmaf(-500.0f, skey[i], a));

    const float sum = (float)start
                    + 0.5f * (float)(end - start)
                    + 0.5f * (s0 + s1);

    out[(b * NN + t) * CC + c] = sum * (1.0f / (float)NN);
}

extern "C" void kernel_launch(void* const* d_in, const int* in_sizes, int n_in,
                              void* d_out, int out_size)
{
    const float* x = (const float*)d_in[0];
    float* out = (float*)d_out;
    softrank_bucket4_kernel<<<BB * CC, NN>>>(x, out);
}